// round 6
// baseline (speedup 1.0000x reference)
#include <cuda_runtime.h>

#define SIDE   32
#define UNITS  1024
#define BATCH  128
#define TSTEPS 512
#define NT     256
#define MNW    36   // Mn row stride in floats (32 + 4 pad) -> 144B rows, 16B aligned

typedef unsigned long long ull;

#define FMA2(acc, a, m)    asm("fma.rn.f32x2 %0, %1, %2, %0;" : "+l"(acc) : "l"(a), "l"(m))
#define FADD2(d, a, b)     asm("add.rn.f32x2 %0, %1, %2;" : "=l"(d) : "l"(a), "l"(b))
#define PACK2(d, lo, hi)   asm("mov.b64 %0, {%1, %2};" : "=l"(d) : "f"(lo), "f"(hi))
#define UNPACK2(lo, hi, s) asm("mov.b64 {%0, %1}, %2;" : "=f"(lo), "=f"(hi) : "l"(s))

__global__ __launch_bounds__(NT, 1)
void minrnn_kernel(const float* __restrict__ x, const float* __restrict__ b,
                   const float* __restrict__ b2, const float* __restrict__ h0,
                   float* __restrict__ out)
{
    // At[buf][j][r] = A[r][j]  (A^T, 128B rows)
    __shared__ __align__(16) float At[2][SIDE][SIDE];
    // Mn[buf][j][c] = M[j][c]  (natural, padded rows)
    __shared__ __align__(16) float Mn[2][SIDE][MNW];

    const int tid  = threadIdx.x;
    const int bb   = blockIdx.x;
    const int warp = tid >> 5;
    const int lane = tid & 31;
    const int p    = lane >> 2;      // row quad 0..7
    const int js   = lane & 3;       // j-split 0..3 (8 j's each)
    const int r0   = p * 4;
    const int c0   = warp * 4;       // this warp's 4 columns
    const int c    = c0 + js;        // this lane's store column
    const int jb   = js * 8;

    // b2 column pack for A-store: {b2[r0+2rp][c], b2[r0+2rp+1][c]}
    ull b2c[2];
    PACK2(b2c[0], b2[(r0    ) * SIDE + c], b2[(r0 + 1) * SIDE + c]);
    PACK2(b2c[1], b2[(r0 + 2) * SIDE + c], b2[(r0 + 3) * SIDE + c]);

    // M-fill role: thread fills Mn[jm][cmf..cmf+3]  (x offset = tid*4, coalesced)
    const int jm  = tid >> 3;
    const int cmf = (tid & 7) * 4;
    ull bf0, bf1;
    PACK2(bf0, b[jm * SIDE + cmf],     b[jm * SIDE + cmf + 1]);
    PACK2(bf1, b[jm * SIDE + cmf + 2], b[jm * SIDE + cmf + 3]);

    // x prefetch ring, depth 3: x(s) lives in slot s%3
    const float* xbase = x + (size_t)bb * TSTEPS * UNITS + tid * 4;
    float4 xr[3];
#pragma unroll
    for (int s = 0; s < 3; s++) xr[s] = *(const float4*)(xbase + (size_t)s * UNITS);

    // ---- prologue: At[0] = (h0 + b2)^T column c ; Mn[0] = b + x(0) ----
    {
        const float* hp = h0 + bb * UNITS;
        ull v0, v1;
        PACK2(v0, hp[(r0    ) * SIDE + c], hp[(r0 + 1) * SIDE + c]);
        PACK2(v1, hp[(r0 + 2) * SIDE + c], hp[(r0 + 3) * SIDE + c]);
        FADD2(v0, v0, b2c[0]);
        FADD2(v1, v1, b2c[1]);
        ulonglong2 st; st.x = v0; st.y = v1;
        *(ulonglong2*)&At[0][c][r0] = st;
    }
    {
        ull x0, x1, m0, m1;
        PACK2(x0, xr[0].x, xr[0].y); PACK2(x1, xr[0].z, xr[0].w);
        FADD2(m0, x0, bf0); FADD2(m1, x1, bf1);
        ulonglong2 st; st.x = m0; st.y = m1;
        *(ulonglong2*)&Mn[0][jm][cmf] = st;
    }
    __syncthreads();

#pragma unroll 2
    for (int t = 0; t < TSTEPS; t++) {
        const int pb = t & 1;
        const int nb = pb ^ 1;

        // prefetch x(t+3) into slot (t+3)%3 == t%3
        if (t + 3 < TSTEPS)
            xr[t % 3] = *(const float4*)(xbase + (size_t)(t + 3) * UNITS);

        // ---- j-loop: 8 js, diagonal FMA2, 3-stage software pipeline ----
        // acc[rp][0] = {h[rA][c0],   h[rB][c0+1]}   (a * mp0)
        // acc[rp][1] = {h[rA][c0+1], h[rB][c0]}     (a * swap(mp0))
        // acc[rp][2] = {h[rA][c0+2], h[rB][c0+3]}   (a * mp1)
        // acc[rp][3] = {h[rA][c0+3], h[rB][c0+2]}   (a * swap(mp1))
        ull acc[2][4];
#pragma unroll
        for (int rp = 0; rp < 2; rp++)
#pragma unroll
            for (int k = 0; k < 4; k++) acc[rp][k] = 0;

        ulonglong2 sa[3], sm[3];
#pragma unroll
        for (int s = 0; s < 2; s++) {
            sa[s] = *(const ulonglong2*)&At[pb][jb + s][r0];
            sm[s] = *(const ulonglong2*)&Mn[pb][jb + s][c0];
        }
#pragma unroll
        for (int jj = 0; jj < 8; jj++) {
            if (jj + 2 < 8) {
                const int s = (jj + 2) % 3;
                sa[s] = *(const ulonglong2*)&At[pb][jb + jj + 2][r0];
                sm[s] = *(const ulonglong2*)&Mn[pb][jb + jj + 2][c0];
            }
            const int s = jj % 3;
            float f0, f1, f2, f3;
            ull m0s, m1s;
            UNPACK2(f0, f1, sm[s].x); PACK2(m0s, f1, f0);
            UNPACK2(f2, f3, sm[s].y); PACK2(m1s, f3, f2);
            FMA2(acc[0][0], sa[s].x, sm[s].x);
            FMA2(acc[0][1], sa[s].x, m0s);
            FMA2(acc[0][2], sa[s].x, sm[s].y);
            FMA2(acc[0][3], sa[s].x, m1s);
            FMA2(acc[1][0], sa[s].y, sm[s].x);
            FMA2(acc[1][1], sa[s].y, m0s);
            FMA2(acc[1][2], sa[s].y, sm[s].y);
            FMA2(acc[1][3], sa[s].y, m1s);
        }

        // ---- register-only reduce over js (butterfly xor 1, 2) ----
#pragma unroll
        for (int rp = 0; rp < 2; rp++)
#pragma unroll
            for (int k = 0; k < 4; k++) {
                ull o;
                o = __shfl_xor_sync(0xFFFFFFFFu, acc[rp][k], 1);
                FADD2(acc[rp][k], acc[rp][k], o);
                o = __shfl_xor_sync(0xFFFFFFFFu, acc[rp][k], 2);
                FADD2(acc[rp][k], acc[rp][k], o);
            }

        // ---- extract this lane's column c = c0 + js (rows r0..r0+3) ----
        float lo0, hi0, lo1, hi1, dmy;
        if (js == 0) {
            UNPACK2(lo0, dmy, acc[0][0]); UNPACK2(dmy, hi0, acc[0][1]);
            UNPACK2(lo1, dmy, acc[1][0]); UNPACK2(dmy, hi1, acc[1][1]);
        } else if (js == 1) {
            UNPACK2(lo0, dmy, acc[0][1]); UNPACK2(dmy, hi0, acc[0][0]);
            UNPACK2(lo1, dmy, acc[1][1]); UNPACK2(dmy, hi1, acc[1][0]);
        } else if (js == 2) {
            UNPACK2(lo0, dmy, acc[0][2]); UNPACK2(dmy, hi0, acc[0][3]);
            UNPACK2(lo1, dmy, acc[1][2]); UNPACK2(dmy, hi1, acc[1][3]);
        } else {
            UNPACK2(lo0, dmy, acc[0][3]); UNPACK2(dmy, hi0, acc[0][2]);
            UNPACK2(lo1, dmy, acc[1][3]); UNPACK2(dmy, hi1, acc[1][2]);
        }

        if (t + 1 < TSTEPS) {
            // A(t+1) column store: At[nb][c][r0..r3] = h + b2
            ull v0, v1;
            PACK2(v0, lo0, hi0); PACK2(v1, lo1, hi1);
            FADD2(v0, v0, b2c[0]); FADD2(v1, v1, b2c[1]);
            ulonglong2 st; st.x = v0; st.y = v1;
            *(ulonglong2*)&At[nb][c][r0] = st;

            // M(t+1) fill: Mn[nb][jm][cmf..+3] = b + x(t+1)
            const float4 v = xr[(t + 1) % 3];
            ull x0, x1, m0, m1;
            PACK2(x0, v.x, v.y); PACK2(x1, v.z, v.w);
            FADD2(m0, x0, bf0); FADD2(m1, x1, bf1);
            ulonglong2 ms; ms.x = m0; ms.y = m1;
            *(ulonglong2*)&Mn[nb][jm][cmf] = ms;
        } else {
            // final h (without b2) -> GMEM, column-scattered (once)
            float* op = out + bb * UNITS;
            op[(r0    ) * SIDE + c] = lo0;
            op[(r0 + 1) * SIDE + c] = hi0;
            op[(r0 + 2) * SIDE + c] = lo1;
            op[(r0 + 3) * SIDE + c] = hi1;
        }
        __syncthreads();
    }
}

extern "C" void kernel_launch(void* const* d_in, const int* in_sizes, int n_in,
                              void* d_out, int out_size)
{
    const float* x  = (const float*)d_in[0];   // [128, 512, 1024]
    const float* b  = (const float*)d_in[1];   // [1024]
    const float* b2 = (const float*)d_in[2];   // [1024]
    const float* h0 = (const float*)d_in[3];   // [128, 1024]
    float* out = (float*)d_out;                // [128, 1024]
    minrnn_kernel<<<BATCH, NT>>>(x, b, b2, h0, out);
}

// round 7
// speedup vs baseline: 1.3253x; 1.3253x over previous
#include <cuda_runtime.h>

#define SIDE   32
#define UNITS  1024
#define BATCH  128
#define TSTEPS 512
#define NT     256
#define MNW    36   // Mn row stride in floats (144B): j and j+1 never bank-alias

typedef unsigned long long ull;

#define FMA2(acc, a, m)    asm("fma.rn.f32x2 %0, %1, %2, %0;" : "+l"(acc) : "l"(a), "l"(m))
#define FADD2(d, a, b)     asm("add.rn.f32x2 %0, %1, %2;" : "=l"(d) : "l"(a), "l"(b))
#define PACK2(d, lo, hi)   asm("mov.b64 %0, {%1, %2};" : "=l"(d) : "f"(lo), "f"(hi))
#define UNPACK2(lo, hi, s) asm("mov.b64 {%0, %1}, %2;" : "=f"(lo), "=f"(hi) : "l"(s))

__global__ __launch_bounds__(NT, 1)
void minrnn_kernel(const float* __restrict__ x, const float* __restrict__ b,
                   const float* __restrict__ b2, const float* __restrict__ h0,
                   float* __restrict__ out)
{
    // Warp-private A^T: Atw[warp][buf][j][r]  (r = warp's 4 rows), 16B rows.
    // j-loop reads j=2jj,2jj+1 x rs -> 32B contiguous -> 1 wf broadcast.
    __shared__ __align__(16) float Atw[8][2][SIDE][4];
    // Shared M (natural): only block-wide state; built one step ahead.
    __shared__ __align__(16) float Mn[2][SIDE][MNW];

    const int tid  = threadIdx.x;
    const int bb   = blockIdx.x;
    const int warp = tid >> 5;
    const int lane = tid & 31;
    const int js   = lane & 1;          // j parity
    const int kq   = (lane >> 1) & 7;   // column quad
    const int rs   = lane >> 4;         // row pair within warp's 4 rows
    const int rA   = warp * 4 + rs * 2;
    const int rB   = rA + 1;
    const int c0   = kq * 4;
    const int sc0  = c0 + js * 2;       // this lane's 2 store columns
    const int sc1  = sc0 + 1;

    // b2 packs for the store columns: {b2[rA][sc], b2[rB][sc]}
    ull b2a, b2b;
    PACK2(b2a, b2[rA * SIDE + sc0], b2[rB * SIDE + sc0]);
    PACK2(b2b, b2[rA * SIDE + sc1], b2[rB * SIDE + sc1]);

    // M-fill role: thread fills Mn[jm][cmf..cmf+3] (== elements tid*4.., coalesced)
    const int jm  = tid >> 3;
    const int cmf = (tid & 7) * 4;
    ull bf0, bf1;
    PACK2(bf0, b[jm * SIDE + cmf],     b[jm * SIDE + cmf + 1]);
    PACK2(bf1, b[jm * SIDE + cmf + 2], b[jm * SIDE + cmf + 3]);

    // x prefetch ring, depth 3: slot s holds x(t) with t%3==s
    const float* xbase = x + (size_t)bb * TSTEPS * UNITS + tid * 4;
    float4 xr[3];
#pragma unroll
    for (int s = 0; s < 3; s++) xr[s] = *(const float4*)(xbase + (size_t)s * UNITS);

    // ---- prologue: Atw[0] = (h0+b2)^T for store cols ; Mn[0] = b + x(0) ----
    {
        const float* hp = h0 + bb * UNITS;
        ull vA, vB;
        PACK2(vA, hp[rA * SIDE + sc0], hp[rB * SIDE + sc0]);
        PACK2(vB, hp[rA * SIDE + sc1], hp[rB * SIDE + sc1]);
        FADD2(vA, vA, b2a); FADD2(vB, vB, b2b);
        *(ull*)&Atw[warp][0][sc0][rs * 2] = vA;
        *(ull*)&Atw[warp][0][sc1][rs * 2] = vB;

        ull x0, x1, m0, m1;
        PACK2(x0, xr[0].x, xr[0].y); PACK2(x1, xr[0].z, xr[0].w);
        FADD2(m0, x0, bf0); FADD2(m1, x1, bf1);
        ulonglong2 st; st.x = m0; st.y = m1;
        *(ulonglong2*)&Mn[0][jm][cmf] = st;
    }
    __syncthreads();

#pragma unroll 2
    for (int t = 0; t < TSTEPS; t++) {
        const int pb = t & 1;
        const int nb = pb ^ 1;

        // ---- build M(t+1) FIRST (off the recurrence critical path) ----
        if (t + 1 < TSTEPS) {
            const float4 v = xr[(t + 1) % 3];
            ull x0, x1, m0, m1;
            PACK2(x0, v.x, v.y); PACK2(x1, v.z, v.w);
            FADD2(m0, x0, bf0); FADD2(m1, x1, bf1);
            ulonglong2 st; st.x = m0; st.y = m1;
            *(ulonglong2*)&Mn[nb][jm][cmf] = st;
        }
        // prefetch x(t+3) into freed slot
        if (t + 3 < TSTEPS)
            xr[t % 3] = *(const float4*)(xbase + (size_t)(t + 3) * UNITS);

        // ---- j-loop: 16 parity-split iterations, modulo-4 pipeline ----
        // d0 = {rA*c0, rB*c1}, d1 = {rA*c1, rB*c0}, d2 = {rA*c2, rB*c3}, d3 = {rA*c3, rB*c2}
        ull d0 = 0, d1 = 0, d2 = 0, d3 = 0;
        ull sa[4]; ulonglong2 sm[4];
#pragma unroll
        for (int s = 0; s < 3; s++) {
            const int j = 2 * s + js;
            sa[s] = *(const ull*)&Atw[warp][pb][j][rs * 2];
            sm[s] = *(const ulonglong2*)&Mn[pb][j][c0];
        }
#pragma unroll
        for (int jj = 0; jj < 16; jj++) {
            if (jj + 3 < 16) {
                const int s2 = (jj + 3) & 3;
                const int j  = 2 * (jj + 3) + js;
                sa[s2] = *(const ull*)&Atw[warp][pb][j][rs * 2];
                sm[s2] = *(const ulonglong2*)&Mn[pb][j][c0];
            }
            const int s = jj & 3;
            float f0, f1, f2, f3;
            ull ms0, ms1;
            UNPACK2(f0, f1, sm[s].x); PACK2(ms0, f1, f0);
            UNPACK2(f2, f3, sm[s].y); PACK2(ms1, f3, f2);
            FMA2(d0, sa[s], sm[s].x);
            FMA2(d1, sa[s], ms0);
            FMA2(d2, sa[s], sm[s].y);
            FMA2(d3, sa[s], ms1);
        }

        // ---- parity reduce: one bfly(1) per accumulator ----
        {
            ull o;
            o = __shfl_xor_sync(0xFFFFFFFFu, d0, 1); FADD2(d0, d0, o);
            o = __shfl_xor_sync(0xFFFFFFFFu, d1, 1); FADD2(d1, d1, o);
            o = __shfl_xor_sync(0xFFFFFFFFu, d2, 1); FADD2(d2, d2, o);
            o = __shfl_xor_sync(0xFFFFFFFFu, d3, 1); FADD2(d3, d3, o);
        }

        // ---- un-diagonalize this lane's 2 store columns ----
        // js=0: cols c0,c0+1 from (d0,d1); js=1: cols c0+2,c0+3 from (d2,d3)
        const ull da = js ? d2 : d0;
        const ull db = js ? d3 : d1;
        float dal, dah, dbl, dbh;
        UNPACK2(dal, dah, da); UNPACK2(dbl, dbh, db);
        ull vA, vB;
        PACK2(vA, dal, dbh);   // {out[rA][sc0], out[rB][sc0]}
        PACK2(vB, dbl, dah);   // {out[rA][sc1], out[rB][sc1]}

        if (t + 1 < TSTEPS) {
            FADD2(vA, vA, b2a); FADD2(vB, vB, b2b);
            *(ull*)&Atw[warp][nb][sc0][rs * 2] = vA;
            *(ull*)&Atw[warp][nb][sc1][rs * 2] = vB;
        } else {
            float* op = out + bb * UNITS;
            float lo, hi;
            UNPACK2(lo, hi, vA);
            op[rA * SIDE + sc0] = lo; op[rB * SIDE + sc0] = hi;
            UNPACK2(lo, hi, vB);
            op[rA * SIDE + sc1] = lo; op[rB * SIDE + sc1] = hi;
        }
        __syncthreads();   // publishes Mn[nb] (+ At for t+1); the only barrier per step
    }
}

extern "C" void kernel_launch(void* const* d_in, const int* in_sizes, int n_in,
                              void* d_out, int out_size)
{
    const float* x  = (const float*)d_in[0];   // [128, 512, 1024]
    const float* b  = (const float*)d_in[1];   // [1024]
    const float* b2 = (const float*)d_in[2];   // [1024]
    const float* h0 = (const float*)d_in[3];   // [128, 1024]
    float* out = (float*)d_out;                // [128, 1024]
    minrnn_kernel<<<BATCH, NT>>>(x, b, b2, h0, out);
}

// round 8
// speedup vs baseline: 1.6976x; 1.2809x over previous
#include <cuda_runtime.h>

#define SIDE   32
#define UNITS  1024
#define BATCH  128
#define TSTEPS 512
#define NT     256
#define ATW    40   // At row stride (floats): js rows 4 apart -> bank offs {0,8,16,24}
#define MDW    34   // Md row stride (ulls):   js rows 4 apart -> word offs {0,4,8,12}

typedef unsigned long long ull;

#define FMA2(acc, a, m)    asm("fma.rn.f32x2 %0, %1, %2, %0;" : "+l"(acc) : "l"(a), "l"(m))
#define FADD2(d, a, b)     asm("add.rn.f32x2 %0, %1, %2;" : "=l"(d) : "l"(a), "l"(b))
#define PACK2(d, lo, hi)   asm("mov.b64 %0, {%1, %2};" : "=l"(d) : "f"(lo), "f"(hi))
#define UNPACK2(lo, hi, s) asm("mov.b64 {%0, %1}, %2;" : "=f"(lo), "=f"(hi) : "l"(s))

__global__ __launch_bounds__(NT, 1)
void minrnn_kernel(const float* __restrict__ x, const float* __restrict__ b,
                   const float* __restrict__ b2, const float* __restrict__ h0,
                   float* __restrict__ out)
{
    // At[buf][j][r] = A[r][j] (A^T)
    __shared__ __align__(16) float At[2][SIDE][ATW];
    // Md[buf][j][c] = {M[j][c], M[j][c]} (dup for FFMA2)
    __shared__ __align__(16) ull   Md[2][SIDE][MDW];

    const int tid  = threadIdx.x;
    const int bb   = blockIdx.x;
    const int warp = tid >> 5;        // cg: this warp's 4 columns 4w..4w+3
    const int lane = tid & 31;
    const int rg   = lane >> 2;       // row quad 0..7
    const int js   = lane & 3;        // j-split: j = 4jj + js
    const int r0   = rg * 4;
    const int c0   = warp * 4;
    const int cst  = c0 + js;         // this lane's store column

    // b2 packs for store column: {b2[r0+2p][cst], b2[r0+2p+1][cst]}
    ull b2s0, b2s1;
    PACK2(b2s0, b2[(r0    ) * SIDE + cst], b2[(r0 + 1) * SIDE + cst]);
    PACK2(b2s1, b2[(r0 + 2) * SIDE + cst], b2[(r0 + 3) * SIDE + cst]);

    // M-fill role: row jm, cols 4cq..4cq+3 (x offset tid*4, coalesced)
    const int jm = tid >> 3;
    const int cq = tid & 7;
    const float bf0 = b[jm * SIDE + 4*cq    ];
    const float bf1 = b[jm * SIDE + 4*cq + 1];
    const float bf2 = b[jm * SIDE + 4*cq + 2];
    const float bf3 = b[jm * SIDE + 4*cq + 3];

    // x prefetch ring, depth 3
    const float* xbase = x + (size_t)bb * TSTEPS * UNITS + tid * 4;
    float4 xr[3];
#pragma unroll
    for (int s = 0; s < 3; s++) xr[s] = *(const float4*)(xbase + (size_t)s * UNITS);

    // ---- prologue: At[0] col cst = h0 + b2 ; Md[0] = dup(b + x(0)) ----
    {
        const float* hp = h0 + bb * UNITS;
        ull v0, v1;
        PACK2(v0, hp[(r0    ) * SIDE + cst], hp[(r0 + 1) * SIDE + cst]);
        PACK2(v1, hp[(r0 + 2) * SIDE + cst], hp[(r0 + 3) * SIDE + cst]);
        FADD2(v0, v0, b2s0); FADD2(v1, v1, b2s1);
        ulonglong2 st; st.x = v0; st.y = v1;
        // store as two 8B halves? No: v0,v1 are floats {r0..r0+3} -> 16B contiguous
        float f0, f1, f2, f3;
        UNPACK2(f0, f1, v0); UNPACK2(f2, f3, v1);
        *(float4*)&At[0][cst][r0] = make_float4(f0, f1, f2, f3);

        float m0 = xr[0].x + bf0, m1 = xr[0].y + bf1;
        float m2 = xr[0].z + bf2, m3 = xr[0].w + bf3;
        ull d0, d1, d2, d3;
        PACK2(d0, m0, m0); PACK2(d1, m1, m1);
        PACK2(d2, m2, m2); PACK2(d3, m3, m3);
        ulonglong2 s0; s0.x = d0; s0.y = d1;
        ulonglong2 s1; s1.x = d2; s1.y = d3;
        *(ulonglong2*)&Md[0][jm][cq * 4]     = s0;
        *(ulonglong2*)&Md[0][jm][cq * 4 + 2] = s1;
    }
    __syncthreads();

#pragma unroll 2
    for (int t = 0; t < TSTEPS; t++) {
        const int pb = t & 1;
        const int nb = pb ^ 1;

        // ---- Md[nb] = dup(b + x(t+1)) first: off the recurrence critical path ----
        if (t + 1 < TSTEPS) {
            const float4 v = xr[(t + 1) % 3];
            float m0 = v.x + bf0, m1 = v.y + bf1, m2 = v.z + bf2, m3 = v.w + bf3;
            ull d0, d1, d2, d3;
            PACK2(d0, m0, m0); PACK2(d1, m1, m1);
            PACK2(d2, m2, m2); PACK2(d3, m3, m3);
            ulonglong2 s0; s0.x = d0; s0.y = d1;
            ulonglong2 s1; s1.x = d2; s1.y = d3;
            *(ulonglong2*)&Md[nb][jm][cq * 4]     = s0;
            *(ulonglong2*)&Md[nb][jm][cq * 4 + 2] = s1;
        }
        if (t + 3 < TSTEPS)
            xr[t % 3] = *(const float4*)(xbase + (size_t)(t + 3) * UNITS);

        // ---- j-loop: 8 iters (j = 4jj+js), modulo-3 software pipeline ----
        // acc[rp][cc] = {h[r0+2rp][c0+cc], h[r0+2rp+1][c0+cc]}  (partial over j≡js)
        ull acc[2][4];
#pragma unroll
        for (int rp = 0; rp < 2; rp++)
#pragma unroll
            for (int cc = 0; cc < 4; cc++) acc[rp][cc] = 0;

        ulonglong2 sa[3], sm0[3], sm1[3];
#pragma unroll
        for (int s = 0; s < 2; s++) {
            const int j = 4 * s + js;
            sa[s]  = *(const ulonglong2*)&At[pb][j][r0];     // floats r0..r0+3 as 2 ull
            sm0[s] = *(const ulonglong2*)&Md[pb][j][c0];
            sm1[s] = *(const ulonglong2*)&Md[pb][j][c0 + 2];
        }
#pragma unroll
        for (int jj = 0; jj < 8; jj++) {
            if (jj + 2 < 8) {
                const int s = (jj + 2) % 3;
                const int j = 4 * (jj + 2) + js;
                sa[s]  = *(const ulonglong2*)&At[pb][j][r0];
                sm0[s] = *(const ulonglong2*)&Md[pb][j][c0];
                sm1[s] = *(const ulonglong2*)&Md[pb][j][c0 + 2];
            }
            const int s = jj % 3;
            FMA2(acc[0][0], sa[s].x, sm0[s].x);
            FMA2(acc[0][1], sa[s].x, sm0[s].y);
            FMA2(acc[0][2], sa[s].x, sm1[s].x);
            FMA2(acc[0][3], sa[s].x, sm1[s].y);
            FMA2(acc[1][0], sa[s].y, sm0[s].x);
            FMA2(acc[1][1], sa[s].y, sm0[s].y);
            FMA2(acc[1][2], sa[s].y, sm1[s].x);
            FMA2(acc[1][3], sa[s].y, sm1[s].y);
        }

        // ---- reduce-scatter over js (2 bfly rounds); lane ends with col cst ----
        const bool p1 = (js & 1) != 0;
        ull ka0 = p1 ? acc[0][1] : acc[0][0], sa0 = p1 ? acc[0][0] : acc[0][1];
        ull ka1 = p1 ? acc[1][1] : acc[1][0], sa1 = p1 ? acc[1][0] : acc[1][1];
        ull kb0 = p1 ? acc[0][3] : acc[0][2], sb0 = p1 ? acc[0][2] : acc[0][3];
        ull kb1 = p1 ? acc[1][3] : acc[1][2], sb1 = p1 ? acc[1][2] : acc[1][3];
        ull g;
        g = __shfl_xor_sync(0xFFFFFFFFu, sa0, 1); FADD2(ka0, ka0, g);
        g = __shfl_xor_sync(0xFFFFFFFFu, sa1, 1); FADD2(ka1, ka1, g);
        g = __shfl_xor_sync(0xFFFFFFFFu, sb0, 1); FADD2(kb0, kb0, g);
        g = __shfl_xor_sync(0xFFFFFFFFu, sb1, 1); FADD2(kb1, kb1, g);
        const bool p2 = (js & 2) != 0;
        ull k0 = p2 ? kb0 : ka0, s0 = p2 ? ka0 : kb0;
        ull k1 = p2 ? kb1 : ka1, s1 = p2 ? ka1 : kb1;
        g = __shfl_xor_sync(0xFFFFFFFFu, s0, 2); FADD2(k0, k0, g);
        g = __shfl_xor_sync(0xFFFFFFFFu, s1, 2); FADD2(k1, k1, g);
        // k0 = {h[r0][cst], h[r0+1][cst]}, k1 = {h[r0+2][cst], h[r0+3][cst]}

        if (t + 1 < TSTEPS) {
            FADD2(k0, k0, b2s0); FADD2(k1, k1, b2s1);
            float f0, f1, f2, f3;
            UNPACK2(f0, f1, k0); UNPACK2(f2, f3, k1);
            *(float4*)&At[nb][cst][r0] = make_float4(f0, f1, f2, f3);
        } else {
            float f0, f1, f2, f3;
            UNPACK2(f0, f1, k0); UNPACK2(f2, f3, k1);
            float* op = out + bb * UNITS;
            op[(r0    ) * SIDE + cst] = f0;
            op[(r0 + 1) * SIDE + cst] = f1;
            op[(r0 + 2) * SIDE + cst] = f2;
            op[(r0 + 3) * SIDE + cst] = f3;
        }
        __syncthreads();   // single barrier: publishes At[nb] + Md[nb]
    }
}

extern "C" void kernel_launch(void* const* d_in, const int* in_sizes, int n_in,
                              void* d_out, int out_size)
{
    const float* x  = (const float*)d_in[0];   // [128, 512, 1024]
    const float* b  = (const float*)d_in[1];   // [1024]
    const float* b2 = (const float*)d_in[2];   // [1024]
    const float* h0 = (const float*)d_in[3];   // [128, 1024]
    float* out = (float*)d_out;                // [128, 1024]
    minrnn_kernel<<<BATCH, NT>>>(x, b, b2, h0, out);
}

// round 9
// speedup vs baseline: 1.7434x; 1.0270x over previous
#include <cuda_runtime.h>

#define SIDE   32
#define UNITS  1024
#define BATCH  128
#define TSTEPS 512
#define NT     128
#define ROWS   16   // rows per CTA (2 CTAs per batch)
#define ATW    20   // At row stride (floats) -> store phases at minimum
#define MDW    34   // Md row stride (ulls)
#define PSW    6    // Psh row stride (ulls): 4 data + 2 pad

typedef unsigned long long ull;

#define FMA2(acc, a, m)    asm("fma.rn.f32x2 %0, %1, %2, %0;" : "+l"(acc) : "l"(a), "l"(m))
#define FADD2(d, a, b)     asm("add.rn.f32x2 %0, %1, %2;" : "=l"(d) : "l"(a), "l"(b))
#define PACK2(d, lo, hi)   asm("mov.b64 %0, {%1, %2};" : "=l"(d) : "f"(lo), "f"(hi))
#define UNPACK2(lo, hi, s) asm("mov.b64 {%0, %1}, %2;" : "=f"(lo), "=f"(hi) : "l"(s))

__global__ __launch_bounds__(NT, 2)
void minrnn_kernel(const float* __restrict__ x, const float* __restrict__ b,
                   const float* __restrict__ b2, const float* __restrict__ h0,
                   float* __restrict__ out)
{
    // At[buf][j][r] = A[Rbase+r][j], r = 0..15 (this CTA's rows)
    __shared__ __align__(16) float At[2][SIDE][ATW];
    // Md[buf][j][c] = {M[j][c], M[j][c]} (dup for FFMA2), full 32x32
    __shared__ __align__(16) ull   Md[2][SIDE][MDW];
    // partial exchange jh1 -> jh0
    __shared__ __align__(16) ull   Psh[64][PSW];

    const int tid   = threadIdx.x;
    const int bb    = blockIdx.x >> 1;
    const int Rbase = (blockIdx.x & 1) * ROWS;
    const int pos   = tid & 63;      // tile position
    const int jh    = tid >> 6;      // j-half: 0 -> j 0..15, 1 -> j 16..31
    const int rg    = pos & 3;       // row quad (local rows 4rg..4rg+3)
    const int cp    = pos >> 2;      // col pair (cols 2cp, 2cp+1)
    const int r0    = rg * 4;
    const int c0    = cp * 2;        // also ull index into Md row
    const int jb    = jh * 16;

    // b2 packs (jh0 only uses them): b2p[p][cc] over global rows Rbase+r0+2p..
    ull b2p[2][2];
#pragma unroll
    for (int p = 0; p < 2; p++)
#pragma unroll
        for (int cc = 0; cc < 2; cc++)
            PACK2(b2p[p][cc], b2[(Rbase + r0 + 2*p) * SIDE + c0 + cc],
                              b2[(Rbase + r0 + 2*p + 1) * SIDE + c0 + cc]);

    // M-fill role: row jm (0..31), cols 8cf..8cf+7  (x offset = tid*8, coalesced)
    const int jm = tid >> 2;
    const int cf = tid & 3;
    ull bfp[4];
    {
        const float* bp = b + jm * SIDE + cf * 8;
#pragma unroll
        for (int e = 0; e < 4; e++) PACK2(bfp[e], bp[2*e], bp[2*e + 1]);
    }

    // x prefetch ring, depth 3 (32B/thread/step)
    const float* xbase = x + (size_t)bb * TSTEPS * UNITS + tid * 8;
    ulonglong2 xr[3][2];
#pragma unroll
    for (int s = 0; s < 3; s++) {
        const ulonglong2* p = (const ulonglong2*)(xbase + (size_t)s * UNITS);
        xr[s][0] = p[0]; xr[s][1] = p[1];
    }

    // ---- prologue: At[0] = (h0+b2)^T (jh0) ; Md[0] = dup(b + x(0)) (all) ----
    if (jh == 0) {
        const float* hp = h0 + bb * UNITS;
#pragma unroll
        for (int cc = 0; cc < 2; cc++) {
            ull v0, v1, hk;
            PACK2(hk, hp[(Rbase + r0    ) * SIDE + c0 + cc],
                      hp[(Rbase + r0 + 1) * SIDE + c0 + cc]);
            FADD2(v0, hk, b2p[0][cc]);
            PACK2(hk, hp[(Rbase + r0 + 2) * SIDE + c0 + cc],
                      hp[(Rbase + r0 + 3) * SIDE + c0 + cc]);
            FADD2(v1, hk, b2p[1][cc]);
            float f0, f1, f2, f3;
            UNPACK2(f0, f1, v0); UNPACK2(f2, f3, v1);
            *(float4*)&At[0][c0 + cc][r0] = make_float4(f0, f1, f2, f3);
        }
    }
    {
        const ull xs[4] = { xr[0][0].x, xr[0][0].y, xr[0][1].x, xr[0][1].y };
#pragma unroll
        for (int e = 0; e < 4; e++) {
            ull m, d0, d1; float f0, f1;
            FADD2(m, xs[e], bfp[e]);
            UNPACK2(f0, f1, m);
            PACK2(d0, f0, f0); PACK2(d1, f1, f1);
            ulonglong2 st; st.x = d0; st.y = d1;
            *(ulonglong2*)&Md[0][jm][cf * 8 + 2*e] = st;
        }
    }
    __syncthreads();

#pragma unroll 2
    for (int t = 0; t < TSTEPS; t++) {
        const int pb = t & 1;
        const int nb = pb ^ 1;

        // ---- Md[nb] = dup(b + x(t+1)): input-only, off the critical path ----
        if (t + 1 < TSTEPS) {
            const int s = (t + 1) % 3;
            const ull xs[4] = { xr[s][0].x, xr[s][0].y, xr[s][1].x, xr[s][1].y };
#pragma unroll
            for (int e = 0; e < 4; e++) {
                ull m, d0, d1; float f0, f1;
                FADD2(m, xs[e], bfp[e]);
                UNPACK2(f0, f1, m);
                PACK2(d0, f0, f0); PACK2(d1, f1, f1);
                ulonglong2 st; st.x = d0; st.y = d1;
                *(ulonglong2*)&Md[nb][jm][cf * 8 + 2*e] = st;
            }
        }
        if (t + 3 < TSTEPS) {
            const ulonglong2* p = (const ulonglong2*)(xbase + (size_t)(t + 3) * UNITS);
            xr[t % 3][0] = p[0]; xr[t % 3][1] = p[1];
        }

        // ---- j-loop: 16 iters over this warp's j-half, modulo-3 pipeline ----
        ull a00 = 0, a01 = 0, a10 = 0, a11 = 0;
        ulonglong2 sa[3]; ulonglong2 sm[3];
#pragma unroll
        for (int s = 0; s < 2; s++) {
            sa[s] = *(const ulonglong2*)&At[pb][jb + s][r0];  // rows r0..r0+3
            sm[s] = *(const ulonglong2*)&Md[pb][jb + s][c0];  // cols c0,c0+1 dup
        }
#pragma unroll
        for (int jj = 0; jj < 16; jj++) {
            if (jj + 2 < 16) {
                const int s = (jj + 2) % 3;
                sa[s] = *(const ulonglong2*)&At[pb][jb + jj + 2][r0];
                sm[s] = *(const ulonglong2*)&Md[pb][jb + jj + 2][c0];
            }
            const int s = jj % 3;
            FMA2(a00, sa[s].x, sm[s].x);   // rows r0,r0+1   x col c0
            FMA2(a01, sa[s].x, sm[s].y);   // rows r0,r0+1   x col c0+1
            FMA2(a10, sa[s].y, sm[s].x);   // rows r0+2,r0+3 x col c0
            FMA2(a11, sa[s].y, sm[s].y);   // rows r0+2,r0+3 x col c0+1
        }

        // jh1 publishes partials
        if (jh == 1) {
            ulonglong2 st;
            st.x = a00; st.y = a01; *(ulonglong2*)&Psh[pos][0] = st;
            st.x = a10; st.y = a11; *(ulonglong2*)&Psh[pos][2] = st;
        }
        __syncthreads();   // bar0: buf-pb reads done; partials visible

        if (jh == 0) {
            ulonglong2 q0 = *(const ulonglong2*)&Psh[pos][0];
            ulonglong2 q1 = *(const ulonglong2*)&Psh[pos][2];
            FADD2(a00, a00, q0.x); FADD2(a01, a01, q0.y);
            FADD2(a10, a10, q1.x); FADD2(a11, a11, q1.y);
            if (t + 1 < TSTEPS) {
                // A(t+1) = h + b2 -> At[nb]  (column stores, 2x STS.128)
                ull v0, v1;
                float f0, f1, f2, f3;
                FADD2(v0, a00, b2p[0][0]); FADD2(v1, a10, b2p[1][0]);
                UNPACK2(f0, f1, v0); UNPACK2(f2, f3, v1);
                *(float4*)&At[nb][c0][r0] = make_float4(f0, f1, f2, f3);
                FADD2(v0, a01, b2p[0][1]); FADD2(v1, a11, b2p[1][1]);
                UNPACK2(f0, f1, v0); UNPACK2(f2, f3, v1);
                *(float4*)&At[nb][c0 + 1][r0] = make_float4(f0, f1, f2, f3);
            } else {
                // final h (no b2) -> GMEM
                float l0, u0, l1, u1;
                float* op = out + bb * UNITS + Rbase * SIDE;
                UNPACK2(l0, u0, a00); UNPACK2(l1, u1, a01);
                *(float2*)(op + (r0    ) * SIDE + c0) = make_float2(l0, l1);
                *(float2*)(op + (r0 + 1) * SIDE + c0) = make_float2(u0, u1);
                UNPACK2(l0, u0, a10); UNPACK2(l1, u1, a11);
                *(float2*)(op + (r0 + 2) * SIDE + c0) = make_float2(l0, l1);
                *(float2*)(op + (r0 + 3) * SIDE + c0) = make_float2(u0, u1);
            }
        }
        __syncthreads();   // bar1: At[nb] + Md[nb] published
    }
}

extern "C" void kernel_launch(void* const* d_in, const int* in_sizes, int n_in,
                              void* d_out, int out_size)
{
    const float* x  = (const float*)d_in[0];   // [128, 512, 1024]
    const float* b  = (const float*)d_in[1];   // [1024]
    const float* b2 = (const float*)d_in[2];   // [1024]
    const float* h0 = (const float*)d_in[3];   // [128, 1024]
    float* out = (float*)d_out;                // [128, 1024]
    minrnn_kernel<<<BATCH * 2, NT>>>(x, b, b2, h0, out);
}

// round 10
// speedup vs baseline: 1.7542x; 1.0062x over previous
#include <cuda_runtime.h>

#define SIDE   32
#define UNITS  1024
#define BATCH  128
#define TSTEPS 512
#define NT     128
#define ROWS   16   // rows per CTA (2 CTAs per batch)
#define ATW    20   // At row stride (floats) -> store phases at minimum
#define MDW    34   // Md row stride (ulls)
#define PSW    6    // Psh row stride (ulls): 4 data + 2 pad

typedef unsigned long long ull;

#define FMA2(acc, a, m)    asm("fma.rn.f32x2 %0, %1, %2, %0;" : "+l"(acc) : "l"(a), "l"(m))
#define FADD2(d, a, b)     asm("add.rn.f32x2 %0, %1, %2;" : "=l"(d) : "l"(a), "l"(b))
#define PACK2(d, lo, hi)   asm("mov.b64 %0, {%1, %2};" : "=l"(d) : "f"(lo), "f"(hi))
#define UNPACK2(lo, hi, s) asm("mov.b64 {%0, %1}, %2;" : "=f"(lo), "=f"(hi) : "l"(s))

__global__ __launch_bounds__(NT, 2)
void minrnn_kernel(const float* __restrict__ x, const float* __restrict__ b,
                   const float* __restrict__ b2, const float* __restrict__ h0,
                   float* __restrict__ out)
{
    // At[buf][j][r] = A[Rbase+r][j], r = 0..15 (this CTA's rows)
    __shared__ __align__(16) float At[2][SIDE][ATW];
    // Md[buf][j][c] = {M[j][c], M[j][c]} (dup for FFMA2), full 32x32
    __shared__ __align__(16) ull   Md[2][SIDE][MDW];
    // partial exchange jh1 -> jh0
    __shared__ __align__(16) ull   Psh[64][PSW];

    const int tid   = threadIdx.x;
    const int bb    = blockIdx.x >> 1;
    const int Rbase = (blockIdx.x & 1) * ROWS;
    const int pos   = tid & 63;      // tile position
    const int jh    = tid >> 6;      // j-half: 0 -> j 0..15, 1 -> j 16..31
    const int rg    = pos & 3;       // row quad (local rows 4rg..4rg+3)
    const int cp    = pos >> 2;      // col pair (cols 2cp, 2cp+1)
    const int r0    = rg * 4;
    const int c0    = cp * 2;        // also ull index into Md row
    const int jb    = jh * 16;

    // b2 packs (jh0 only uses them): b2p[p][cc] over global rows Rbase+r0+2p..
    ull b2p[2][2];
#pragma unroll
    for (int p = 0; p < 2; p++)
#pragma unroll
        for (int cc = 0; cc < 2; cc++)
            PACK2(b2p[p][cc], b2[(Rbase + r0 + 2*p) * SIDE + c0 + cc],
                              b2[(Rbase + r0 + 2*p + 1) * SIDE + c0 + cc]);

    // M-fill role: row jm (0..31), cols 8cf..8cf+7  (x offset = tid*8, coalesced)
    const int jm = tid >> 2;
    const int cf = tid & 3;
    ull bfp[4];
    {
        const float* bp = b + jm * SIDE + cf * 8;
#pragma unroll
        for (int e = 0; e < 4; e++) PACK2(bfp[e], bp[2*e], bp[2*e + 1]);
    }

    // x prefetch ring, depth 3 (32B/thread/step)
    const float* xbase = x + (size_t)bb * TSTEPS * UNITS + tid * 8;
    ulonglong2 xr[3][2];
#pragma unroll
    for (int s = 0; s < 3; s++) {
        const ulonglong2* p = (const ulonglong2*)(xbase + (size_t)s * UNITS);
        xr[s][0] = p[0]; xr[s][1] = p[1];
    }

    // ---- prologue: At[0] = (h0+b2)^T (jh0) ; Md[0] = dup(b + x(0)) (all) ----
    if (jh == 0) {
        const float* hp = h0 + bb * UNITS;
#pragma unroll
        for (int cc = 0; cc < 2; cc++) {
            ull v0, v1, hk;
            PACK2(hk, hp[(Rbase + r0    ) * SIDE + c0 + cc],
                      hp[(Rbase + r0 + 1) * SIDE + c0 + cc]);
            FADD2(v0, hk, b2p[0][cc]);
            PACK2(hk, hp[(Rbase + r0 + 2) * SIDE + c0 + cc],
                      hp[(Rbase + r0 + 3) * SIDE + c0 + cc]);
            FADD2(v1, hk, b2p[1][cc]);
            float f0, f1, f2, f3;
            UNPACK2(f0, f1, v0); UNPACK2(f2, f3, v1);
            *(float4*)&At[0][c0 + cc][r0] = make_float4(f0, f1, f2, f3);
        }
    }
    {
        const ull xs[4] = { xr[0][0].x, xr[0][0].y, xr[0][1].x, xr[0][1].y };
#pragma unroll
        for (int e = 0; e < 4; e++) {
            ull m, d0, d1; float f0, f1;
            FADD2(m, xs[e], bfp[e]);
            UNPACK2(f0, f1, m);
            PACK2(d0, f0, f0); PACK2(d1, f1, f1);
            ulonglong2 st; st.x = d0; st.y = d1;
            *(ulonglong2*)&Md[0][jm][cf * 8 + 2*e] = st;
        }
    }
    __syncthreads();

#pragma unroll 2
    for (int t = 0; t < TSTEPS; t++) {
        const int pb = t & 1;
        const int nb = pb ^ 1;

        // ---- Md[nb] = dup(b + x(t+1)): input-only, off the critical path ----
        if (t + 1 < TSTEPS) {
            const int s = (t + 1) % 3;
            const ull xs[4] = { xr[s][0].x, xr[s][0].y, xr[s][1].x, xr[s][1].y };
#pragma unroll
            for (int e = 0; e < 4; e++) {
                ull m, d0, d1; float f0, f1;
                FADD2(m, xs[e], bfp[e]);
                UNPACK2(f0, f1, m);
                PACK2(d0, f0, f0); PACK2(d1, f1, f1);
                ulonglong2 st; st.x = d0; st.y = d1;
                *(ulonglong2*)&Md[nb][jm][cf * 8 + 2*e] = st;
            }
        }
        if (t + 3 < TSTEPS) {
            const ulonglong2* p = (const ulonglong2*)(xbase + (size_t)(t + 3) * UNITS);
            xr[t % 3][0] = p[0]; xr[t % 3][1] = p[1];
        }

        // ---- j-loop: 16 iters over this warp's j-half, modulo-3 pipeline ----
        ull a00 = 0, a01 = 0, a10 = 0, a11 = 0;
        ulonglong2 sa[3]; ulonglong2 sm[3];
#pragma unroll
        for (int s = 0; s < 2; s++) {
            sa[s] = *(const ulonglong2*)&At[pb][jb + s][r0];  // rows r0..r0+3
            sm[s] = *(const ulonglong2*)&Md[pb][jb + s][c0];  // cols c0,c0+1 dup
        }
#pragma unroll
        for (int jj = 0; jj < 16; jj++) {
            if (jj + 2 < 16) {
                const int s = (jj + 2) % 3;
                sa[s] = *(const ulonglong2*)&At[pb][jb + jj + 2][r0];
                sm[s] = *(const ulonglong2*)&Md[pb][jb + jj + 2][c0];
            }
            const int s = jj % 3;
            FMA2(a00, sa[s].x, sm[s].x);   // rows r0,r0+1   x col c0
            FMA2(a01, sa[s].x, sm[s].y);   // rows r0,r0+1   x col c0+1
            FMA2(a10, sa[s].y, sm[s].x);   // rows r0+2,r0+3 x col c0
            FMA2(a11, sa[s].y, sm[s].y);   // rows r0+2,r0+3 x col c0+1
        }

        // jh1 publishes partials
        if (jh == 1) {
            ulonglong2 st;
            st.x = a00; st.y = a01; *(ulonglong2*)&Psh[pos][0] = st;
            st.x = a10; st.y = a11; *(ulonglong2*)&Psh[pos][2] = st;
        }
        __syncthreads();   // bar0: buf-pb reads done; partials visible

        if (jh == 0) {
            ulonglong2 q0 = *(const ulonglong2*)&Psh[pos][0];
            ulonglong2 q1 = *(const ulonglong2*)&Psh[pos][2];
            FADD2(a00, a00, q0.x); FADD2(a01, a01, q0.y);
            FADD2(a10, a10, q1.x); FADD2(a11, a11, q1.y);
            if (t + 1 < TSTEPS) {
                // A(t+1) = h + b2 -> At[nb]  (column stores, 2x STS.128)
                ull v0, v1;
                float f0, f1, f2, f3;
                FADD2(v0, a00, b2p[0][0]); FADD2(v1, a10, b2p[1][0]);
                UNPACK2(f0, f1, v0); UNPACK2(f2, f3, v1);
                *(float4*)&At[nb][c0][r0] = make_float4(f0, f1, f2, f3);
                FADD2(v0, a01, b2p[0][1]); FADD2(v1, a11, b2p[1][1]);
                UNPACK2(f0, f1, v0); UNPACK2(f2, f3, v1);
                *(float4*)&At[nb][c0 + 1][r0] = make_float4(f0, f1, f2, f3);
            } else {
                // final h (no b2) -> GMEM
                float l0, u0, l1, u1;
                float* op = out + bb * UNITS + Rbase * SIDE;
                UNPACK2(l0, u0, a00); UNPACK2(l1, u1, a01);
                *(float2*)(op + (r0    ) * SIDE + c0) = make_float2(l0, l1);
                *(float2*)(op + (r0 + 1) * SIDE + c0) = make_float2(u0, u1);
                UNPACK2(l0, u0, a10); UNPACK2(l1, u1, a11);
                *(float2*)(op + (r0 + 2) * SIDE + c0) = make_float2(l0, l1);
                *(float2*)(op + (r0 + 3) * SIDE + c0) = make_float2(u0, u1);
            }
        }
        __syncthreads();   // bar1: At[nb] + Md[nb] published
    }
}

extern "C" void kernel_launch(void* const* d_in, const int* in_sizes, int n_in,
                              void* d_out, int out_size)
{
    const float* x  = (const float*)d_in[0];   // [128, 512, 1024]
    const float* b  = (const float*)d_in[1];   // [1024]
    const float* b2 = (const float*)d_in[2];   // [1024]
    const float* h0 = (const float*)d_in[3];   // [128, 1024]
    float* out = (float*)d_out;                // [128, 1024]
    minrnn_kernel<<<BATCH * 2, NT>>>(x, b, b2, h0, out);
}